// round 5
// baseline (speedup 1.0000x reference)
#include <cuda_runtime.h>
#include <math.h>

#define B_    64
#define T_    12
#define N_    800
#define CIN_  2
#define H_    64
#define HOR_  12
#define TC_H  2
#define KAPPA_ 0.05f
#define NB    (N_*B_)      /* 51200 rows (node-major, batch inner) */

// packed fp32 FMA (Blackwell dual-fp32 pipe) — bit-exact fp32 per lane
__device__ __forceinline__ float2 ffma2(float2 a, float2 b, float2 c) {
    float2 d;
    asm("fma.rn.f32x2 %0, %1, %2, %3;"
        : "=l"(reinterpret_cast<unsigned long long&>(d))
        : "l"(reinterpret_cast<unsigned long long&>(a)),
          "l"(reinterpret_cast<unsigned long long&>(b)),
          "l"(reinterpret_cast<unsigned long long&>(c)));
    return d;
}

// ---------------- scratch (device globals; no allocs allowed) ----------------
__device__ float g_A2[1600*800];              // rows 0..799: G^T ; 800..1599: 2 G^T G^T - I
__device__ float g_EMBX[B_*T_*N_*TC_H];
__device__ float g_EMBY[B_*HOR_*N_*TC_H];
__device__ float g_H0[NB*H_];
__device__ float g_H1[NB*H_];
__device__ float g_F [NB*384];                // gate features [X|Y1|Y2]
__device__ float g_FC[NB*384];                // candidate features
__device__ float g_UR[NB*128];                // sigmoid(u|r)
__device__ float g_GO[NB*CIN_];
__device__ float g_Q [B_*8];
__device__ float g_ATTM[B_*N_*8];
__device__ float g_WG[4][384*128];            // folded gate weights
__device__ float g_WC[4][384*64];             // folded candidate weights

// ---------------- setup kernels ----------------
__global__ void transpose_kernel(const float* __restrict__ G) {
    __shared__ float t[32][33];
    int x = blockIdx.x*32 + threadIdx.x, y = blockIdx.y*32 + threadIdx.y;
    t[threadIdx.y][threadIdx.x] = G[y*N_ + x];
    __syncthreads();
    int x2 = blockIdx.y*32 + threadIdx.x, y2 = blockIdx.x*32 + threadIdx.y;
    g_A2[y2*N_ + x2] = t[threadIdx.x][threadIdx.y];
}

// G2 = 2 * GT @ GT - I   (setup-only, scalar FFMA is fine)
__global__ void __launch_bounds__(256) g2_kernel() {
    __shared__ float As[8][128], Bs[8][128];
    int tid = threadIdx.x;
    int i0 = blockIdx.y*128, j0 = blockIdx.x*128;
    int ty = tid>>4, tx = tid&15, rl = ty*4, cl = tx*4;
    int ar = tid>>1, ac = (tid&1)*4;
    int bk = tid>>5, bj = (tid&31)*4;
    float acc[8][8];
    #pragma unroll
    for (int i=0;i<8;i++) {
        #pragma unroll
        for (int j=0;j<8;j++) acc[i][j]=0.f;
    }
    for (int k0=0;k0<N_;k0+=8) {
        float4 av = make_float4(0,0,0,0);
        if (i0+ar < N_) av = *(const float4*)&g_A2[(long)(i0+ar)*N_ + k0+ac];
        As[ac+0][ar]=av.x; As[ac+1][ar]=av.y; As[ac+2][ar]=av.z; As[ac+3][ar]=av.w;
        float4 bv = make_float4(0,0,0,0);
        if (j0+bj < N_) bv = *(const float4*)&g_A2[(long)(k0+bk)*N_ + j0+bj];
        *(float4*)&Bs[bk][bj] = bv;
        __syncthreads();
        #pragma unroll
        for (int kk=0;kk<8;kk++) {
            float a[8], b[8];
            *(float4*)a     = *(const float4*)&As[kk][rl];
            *(float4*)(a+4) = *(const float4*)&As[kk][rl+64];
            *(float4*)b     = *(const float4*)&Bs[kk][cl];
            *(float4*)(b+4) = *(const float4*)&Bs[kk][cl+64];
            #pragma unroll
            for (int i=0;i<8;i++) {
                #pragma unroll
                for (int j=0;j<8;j++) acc[i][j] += a[i]*b[j];
            }
        }
        __syncthreads();
    }
    #pragma unroll
    for (int i=0;i<8;i++) {
        int r = i0 + (i<4 ? rl+i : 64+rl+i-4);
        if (r >= N_) continue;
        #pragma unroll
        for (int j=0;j<8;j++) {
            int c = j0 + (j<4 ? cl+j : 64+cl+j-4);
            if (c >= N_) continue;
            g_A2[(long)(N_+r)*N_ + c] = 2.f*acc[i][j] - (r==c ? 1.f : 0.f);
        }
    }
}

__global__ void fold_kernel(const float* __restrict__ W, int isGate, int widx, int P, int O) {
    float* Wf = isGate ? g_WG[widx] : g_WC[widx];
    int idx = blockIdx.x*256 + threadIdx.x;
    int tot = 3*P*O;
    if (idx >= tot) return;
    int row = idx / O, o = idx % O;
    int k = row / P, p = row % P;
    float v;
    if (k == 0) v = W[idx] + KAPPA_*(W[(P+p)*O + o] + W[(2*P+p)*O + o]);
    else        v = (1.f - KAPPA_)*W[idx];
    Wf[idx] = v;
}

__global__ void mlp_kernel(const float* __restrict__ Tin,
                           const float* __restrict__ W1, const float* __restrict__ b1,
                           const float* __restrict__ W2, const float* __restrict__ b2,
                           int dsel) {
    float* out = dsel ? g_EMBY : g_EMBX;
    int r = blockIdx.x, tid = threadIdx.x;
    __shared__ float tin[60];
    __shared__ float hid[10];
    if (tid < 60) tin[tid] = Tin[(long)r*60 + tid];
    __syncthreads();
    if (tid < 10) {
        float s = b1[tid];
        for (int i = 0; i < 60; i++) s += tin[i]*W1[i*10 + tid];
        hid[tid] = s;
    }
    __syncthreads();
    for (int o = tid; o < N_*TC_H; o += 256) {
        float s = b2[o];
        #pragma unroll
        for (int j = 0; j < 10; j++) s += hid[j]*W2[j*(N_*TC_H) + o];
        out[(long)r*(N_*TC_H) + o] = s;
    }
}

__global__ void zero_state() {
    int i = blockIdx.x*256 + threadIdx.x;
    if (i < NB*H_) { g_H0[i] = 0.f; g_H1[i] = 0.f; }
    if (i < NB*CIN_) g_GO[i] = 0.f;
}

// ---------------- feature builders ----------------
__global__ void build_xh0(const float* __restrict__ xs, int t, int isDec) {
    int idx = blockIdx.x*256 + threadIdx.x;
    if (idx >= NB*68) return;
    int c = idx % 68, row = idx / 68;
    int b = row % B_, n = row / B_;
    float v;
    if (isDec) {
        if (c < 2)      v = g_GO[row*2 + c];
        else if (c < 4) v = g_EMBY[(long)(b*HOR_ + t)*(N_*TC_H) + n*TC_H + (c-2)];
        else            v = g_H0[(long)row*64 + (c-4)];
    } else {
        if (c < 2)      v = xs[((long)(b*T_ + t)*N_ + n)*CIN_ + c];
        else if (c < 4) v = g_EMBX[(long)(b*T_ + t)*(N_*TC_H) + n*TC_H + (c-2)];
        else            v = g_H0[(long)row*64 + (c-4)];
    }
    g_F[(long)row*204 + c] = v;
}

__global__ void build_xh1() {
    int idx = blockIdx.x*256 + threadIdx.x;
    if (idx >= NB*128) return;
    int c = idx % 128, row = idx / 128;
    float v = (c < 64) ? g_H0[(long)row*64 + c] : g_H1[(long)row*64 + (c-64)];
    g_F[(long)row*384 + c] = v;
}

__global__ void build_fc0() {
    int idx = blockIdx.x*256 + threadIdx.x;
    if (idx >= NB*76) return;
    int j = idx % 76, row = idx / 76;
    long base = (long)row*204;
    if (j < 4)       g_FC[base + j] = g_F[base + j];
    else if (j < 68) { int c = j-4; g_FC[base + j] = g_UR[(long)row*128 + 64 + c]*g_H0[(long)row*64 + c]; }
    else if (j < 72) { int c = 68 + (j-68);  g_FC[base + c] = g_F[base + c]; }
    else             { int c = 136 + (j-72); g_FC[base + c] = g_F[base + c]; }
}

__global__ void build_rh1() {
    int idx = blockIdx.x*256 + threadIdx.x;
    if (idx >= NB*64) return;
    int c = idx & 63, row = idx >> 6;
    g_FC[(long)row*384 + 64 + c] = g_UR[(long)row*128 + 64 + c]*g_H1[(long)row*64 + c];
}

// ---------------- stacked graph propagation: [Y1;Y2] = [GT;G2] @ X -------------
// f32x2 core: acc packs adjacent A-rows; B stored splat-duplicated in smem.
__global__ void __launch_bounds__(256,2) prop2(int bufSel, int CF, int src_off,
                                               int d1, int d2, int Psub) {
    float* buf = bufSel ? g_FC : g_F;
    __shared__ float As [2][8][128];
    __shared__ float Bsd[2][8][256];   // duplicated pairs (b,b)
    int tid = threadIdx.x;
    int n0 = blockIdx.y*128, j0 = blockIdx.x*128;
    int ty = tid>>4, tx = tid&15, rl = ty*4, cl = tx*4;
    int ar = tid>>1, ac = (tid&1)*4;
    int bk = tid>>5, bj = (tid&31)*4;
    int jg = j0 + bj;
    int bo = jg / Psub, co = jg - bo*Psub;
    long rowStride = (long)B_*CF;
    long bcol = (long)bo*CF + src_off + co;
    int arow = n0 + ar;
    bool aval = arow < 1600;

    float2 acc[4][8];
    #pragma unroll
    for (int i=0;i<4;i++) {
        #pragma unroll
        for (int j=0;j<8;j++) acc[i][j] = make_float2(0.f,0.f);
    }

    // prologue: panel 0
    {
        float4 av = aval ? *(const float4*)&g_A2[(long)arow*N_ + ac] : make_float4(0,0,0,0);
        As[0][ac+0][ar]=av.x; As[0][ac+1][ar]=av.y; As[0][ac+2][ar]=av.z; As[0][ac+3][ar]=av.w;
        float4 bv = *(const float4*)&buf[(long)bk*rowStride + bcol];
        *(float4*)&Bsd[0][bk][2*bj]   = make_float4(bv.x,bv.x,bv.y,bv.y);
        *(float4*)&Bsd[0][bk][2*bj+4] = make_float4(bv.z,bv.z,bv.w,bv.w);
    }
    __syncthreads();

    int cur = 0;
    for (int k0 = 8; k0 <= N_; k0 += 8) {
        float4 av2, bv2;
        bool more = k0 < N_;
        if (more) {
            av2 = aval ? *(const float4*)&g_A2[(long)arow*N_ + k0 + ac] : make_float4(0,0,0,0);
            bv2 = *(const float4*)&buf[(long)(k0+bk)*rowStride + bcol];
        }
        #pragma unroll
        for (int kk=0;kk<8;kk++) {
            float4 a0 = *(const float4*)&As[cur][kk][rl];
            float4 a1 = *(const float4*)&As[cur][kk][rl+64];
            float2 ap[4] = { {a0.x,a0.y},{a0.z,a0.w},{a1.x,a1.y},{a1.z,a1.w} };
            float4 b0 = *(const float4*)&Bsd[cur][kk][2*cl];
            float4 b1 = *(const float4*)&Bsd[cur][kk][2*cl+4];
            float4 b2 = *(const float4*)&Bsd[cur][kk][128+2*cl];
            float4 b3 = *(const float4*)&Bsd[cur][kk][128+2*cl+4];
            float2 bs[8] = { {b0.x,b0.y},{b0.z,b0.w},{b1.x,b1.y},{b1.z,b1.w},
                             {b2.x,b2.y},{b2.z,b2.w},{b3.x,b3.y},{b3.z,b3.w} };
            #pragma unroll
            for (int i=0;i<4;i++) {
                #pragma unroll
                for (int j=0;j<8;j++) acc[i][j] = ffma2(ap[i], bs[j], acc[i][j]);
            }
        }
        if (more) {
            int nxt = cur^1;
            As[nxt][ac+0][ar]=av2.x; As[nxt][ac+1][ar]=av2.y;
            As[nxt][ac+2][ar]=av2.z; As[nxt][ac+3][ar]=av2.w;
            *(float4*)&Bsd[nxt][bk][2*bj]   = make_float4(bv2.x,bv2.x,bv2.y,bv2.y);
            *(float4*)&Bsd[nxt][bk][2*bj+4] = make_float4(bv2.z,bv2.z,bv2.w,bv2.w);
            __syncthreads();
            cur = nxt;
        }
    }

    // epilogue: float4 stores into Y slices
    int cAg = j0 + cl, cBg = j0 + cl + 64;
    int boA = cAg/Psub, coA = cAg - boA*Psub;
    int boB = cBg/Psub, coB = cBg - boB*Psub;
    long colA = (long)boA*CF + coA;
    long colB = (long)boB*CF + coB;
    #pragma unroll
    for (int ii=0;ii<4;ii++) {
        int rbase = n0 + ((ii<2) ? (rl + 2*ii) : (64 + rl + 2*(ii-2)));
        #pragma unroll
        for (int sel=0; sel<2; sel++) {
            int r = rbase + sel;
            if (r >= 1600) continue;
            long base = (r < 800) ? ((long)r*rowStride + d1) : ((long)(r-800)*rowStride + d2);
            float v[8];
            #pragma unroll
            for (int j=0;j<8;j++) v[j] = sel ? acc[ii][j].y : acc[ii][j].x;
            *(float4*)&buf[base + colA] = make_float4(v[0],v[1],v[2],v[3]);
            *(float4*)&buf[base + colB] = make_float4(v[4],v[5],v[6],v[7]);
        }
    }
}

// ---------------- projection GEMM with fused GRU epilogues (f32x2 core) -------
// MODE 0: UR = sigmoid(F @ Wg + bg)   NO=128
// MODE 1: H  = (1-u)h + u*tanh(A @ Wc + bc)  NO=64
// srcMode: 0 = g_F, 1 = g_FC, 2 = parity (k>>6 even -> g_F, odd -> g_FC)
template<int NO, int MODE>
__global__ void __launch_bounds__(256,2) proj2(int srcMode, int CF, int Kdim, int wsel,
                                               const float* __restrict__ bias, int hsel) {
    const float* W = (MODE==0) ? g_WG[wsel] : g_WC[wsel];
    constexpr int TN = (NO==128) ? 8 : 4;
    __shared__ float As [2][8][128];
    __shared__ float Wsd[2][8][2*NO];       // duplicated (w,w) pairs
    int tid = threadIdx.x;
    long row0 = (long)blockIdx.x*128;
    int ty = tid>>4, tx = tid&15, rl = ty*4, cl = tx*4;
    int ar = tid>>1, ac = (tid&1)*4;
    int wk, wc; bool wact;
    if (NO==128) { wk = tid>>5; wc = (tid&31)*4; wact = true; }
    else         { wk = tid>>4; wc = (tid&15)*4; wact = (tid < 128); }

    float2 acc[4][TN];
    #pragma unroll
    for (int i=0;i<4;i++) {
        #pragma unroll
        for (int j=0;j<TN;j++) acc[i][j] = make_float2(0.f,0.f);
    }

    auto loadA = [&](int k0) -> float4 {
        int kg = k0 + ac;
        if (kg >= Kdim) return make_float4(0,0,0,0);
        const float* Ab;
        if (srcMode == 0) Ab = g_F;
        else if (srcMode == 1) Ab = g_FC;
        else Ab = ((kg>>6)&1) ? g_FC : g_F;
        return *(const float4*)&Ab[(row0+ar)*CF + kg];
    };
    auto loadW = [&](int k0) -> float4 {
        int kg = k0 + wk;
        if (!wact || kg >= Kdim) return make_float4(0,0,0,0);
        return *(const float4*)&W[(long)kg*NO + wc];
    };
    auto storeW = [&](int bufi, float4 w) {
        if (!wact) return;
        *(float4*)&Wsd[bufi][wk][2*wc]   = make_float4(w.x,w.x,w.y,w.y);
        *(float4*)&Wsd[bufi][wk][2*wc+4] = make_float4(w.z,w.z,w.w,w.w);
    };

    int KT = ((Kdim + 7)/8)*8;
    {
        float4 av = loadA(0), wv = loadW(0);
        As[0][ac+0][ar]=av.x; As[0][ac+1][ar]=av.y; As[0][ac+2][ar]=av.z; As[0][ac+3][ar]=av.w;
        storeW(0, wv);
    }
    __syncthreads();

    int cur = 0;
    for (int k0 = 8; k0 <= KT; k0 += 8) {
        float4 av2, wv2;
        bool more = k0 < KT;
        if (more) { av2 = loadA(k0); wv2 = loadW(k0); }
        #pragma unroll
        for (int kk=0;kk<8;kk++) {
            float4 a0 = *(const float4*)&As[cur][kk][rl];
            float4 a1 = *(const float4*)&As[cur][kk][rl+64];
            float2 ap[4] = { {a0.x,a0.y},{a0.z,a0.w},{a1.x,a1.y},{a1.z,a1.w} };
            float2 bs[TN];
            {
                float4 w0 = *(const float4*)&Wsd[cur][kk][2*cl];
                float4 w1 = *(const float4*)&Wsd[cur][kk][2*cl+4];
                bs[0] = make_float2(w0.x,w0.y); bs[1] = make_float2(w0.z,w0.w);
                bs[2] = make_float2(w1.x,w1.y); bs[3] = make_float2(w1.z,w1.w);
                if (NO==128) {
                    float4 w2 = *(const float4*)&Wsd[cur][kk][128 + 2*cl];
                    float4 w3 = *(const float4*)&Wsd[cur][kk][128 + 2*cl+4];
                    bs[4] = make_float2(w2.x,w2.y); bs[5] = make_float2(w2.z,w2.w);
                    bs[6] = make_float2(w3.x,w3.y); bs[7] = make_float2(w3.z,w3.w);
                }
            }
            #pragma unroll
            for (int i=0;i<4;i++) {
                #pragma unroll
                for (int j=0;j<TN;j++) acc[i][j] = ffma2(ap[i], bs[j], acc[i][j]);
            }
        }
        if (more) {
            int nxt = cur^1;
            As[nxt][ac+0][ar]=av2.x; As[nxt][ac+1][ar]=av2.y;
            As[nxt][ac+2][ar]=av2.z; As[nxt][ac+3][ar]=av2.w;
            storeW(nxt, wv2);
            __syncthreads();
            cur = nxt;
        }
    }

    float* Hb = hsel ? g_H1 : g_H0;
    #pragma unroll
    for (int ii=0;ii<4;ii++) {
        long rbase = row0 + ((ii<2) ? (rl + 2*ii) : (64 + rl + 2*(ii-2)));
        #pragma unroll
        for (int sel=0; sel<2; sel++) {
            long row = rbase + sel;
            #pragma unroll
            for (int j=0;j<TN;j++) {
                int c = (NO==128) ? ((j<4) ? cl+j : 64+cl+(j-4)) : (cl+j);
                float v = (sel ? acc[ii][j].y : acc[ii][j].x) + bias[c];
                if (MODE == 0) {
                    g_UR[row*128 + c] = 1.f/(1.f + expf(-v));
                } else {
                    float cv = tanhf(v);
                    float u  = g_UR[row*128 + c];
                    float h  = Hb[row*64 + c];
                    Hb[row*64 + c] = (1.f - u)*h + u*cv;
                }
            }
        }
    }
}

// ---------------- decoder memory attention + output projection ----------------
__global__ void query_kernel(const float* __restrict__ Wa) {
    int b = blockIdx.x, tid = threadIdx.x;
    float p[8];
    #pragma unroll
    for (int d = 0; d < 8; d++) p[d] = 0.f;
    for (int idx = tid; idx < N_*H_; idx += 256) {
        int n = idx >> 6, j = idx & 63;
        float v = g_H1[(long)(n*B_ + b)*64 + j];
        const float* w = Wa + (long)idx*8;
        #pragma unroll
        for (int d = 0; d < 8; d++) p[d] += v*w[d];
    }
    #pragma unroll
    for (int d = 0; d < 8; d++)
        for (int off = 16; off > 0; off >>= 1) p[d] += __shfl_down_sync(0xffffffffu, p[d], off);
    __shared__ float sm[8][8];
    int w = tid >> 5, l = tid & 31;
    if (l == 0) { for (int d = 0; d < 8; d++) sm[w][d] = p[d]; }
    __syncthreads();
    if (tid < 8) {
        float s = 0.f;
        for (int ww = 0; ww < 8; ww++) s += sm[ww][tid];
        g_Q[b*8 + tid] = s;
    }
}

__global__ void attm_kernel(const float* __restrict__ mem, const float* __restrict__ fcw) {
    int b = blockIdx.x, tid = threadIdx.x;
    __shared__ float am[8];
    if (tid == 0) {
        float q[8];
        for (int d = 0; d < 8; d++) q[d] = g_Q[b*8 + d];
        float s[4]; float mx = -1e30f;
        for (int m = 0; m < 4; m++) {
            float a = 0.f;
            for (int d = 0; d < 8; d++) a += q[d]*mem[m*8 + d];
            s[m] = a; mx = fmaxf(mx, a);
        }
        float den = 0.f;
        for (int m = 0; m < 4; m++) { s[m] = expf(s[m]-mx); den += s[m]; }
        for (int d = 0; d < 8; d++) {
            float a = 0.f;
            for (int m = 0; m < 4; m++) a += (s[m]/den)*mem[m*8 + d];
            am[d] = a;
        }
    }
    __syncthreads();
    for (int i = tid; i < N_*8; i += 256) {
        float s = 0.f;
        #pragma unroll
        for (int d = 0; d < 8; d++) s += am[d]*fcw[(long)d*(N_*8) + i];
        g_ATTM[(long)b*(N_*8) + i] = s;
    }
}

__global__ void out_kernel(const float* __restrict__ pW, const float* __restrict__ pb,
                           float* __restrict__ outp, int s) {
    int row = blockIdx.x*256 + threadIdx.x;
    if (row >= NB) return;
    int b = row % B_, n = row / B_;
    float a0 = pb[0], a1 = pb[1];
    const float* h = g_H1 + (long)row*64;
    #pragma unroll
    for (int j = 0; j < 64; j++) { float v = h[j]; a0 += v*pW[j*2]; a1 += v*pW[j*2+1]; }
    const float* at = g_ATTM + (long)b*(N_*8) + n*8;
    #pragma unroll
    for (int d = 0; d < 8; d++) { float v = at[d]; a0 += v*pW[(64+d)*2]; a1 += v*pW[(64+d)*2+1]; }
    a0 = fmaxf(a0, 0.f); a1 = fmaxf(a1, 0.f);
    g_GO[row*2] = a0; g_GO[row*2+1] = a1;
    long o = ((long)(b*HOR_ + s)*N_ + n)*CIN_;
    outp[o] = a0; outp[o+1] = a1;
}

// ---------------- orchestration ----------------
extern "C" void kernel_launch(void* const* d_in, const int* in_sizes, int n_in,
                              void* d_out, int out_size) {
    (void)in_sizes; (void)n_in; (void)out_size;
    const float* x_seq = (const float*)d_in[0];
    const float* t_x   = (const float*)d_in[1];
    const float* t_y   = (const float*)d_in[2];
    const float* G     = (const float*)d_in[3];
    const float* eWg0  = (const float*)d_in[4];  const float* ebg0 = (const float*)d_in[5];
    const float* eWc0  = (const float*)d_in[6];  const float* ebc0 = (const float*)d_in[7];
    const float* eWg1  = (const float*)d_in[8];  const float* ebg1 = (const float*)d_in[9];
    const float* eWc1  = (const float*)d_in[10]; const float* ebc1 = (const float*)d_in[11];
    const float* dWg0  = (const float*)d_in[12]; const float* dbg0 = (const float*)d_in[13];
    const float* dWc0  = (const float*)d_in[14]; const float* dbc0 = (const float*)d_in[15];
    const float* dWg1  = (const float*)d_in[16]; const float* dbg1 = (const float*)d_in[17];
    const float* dWc1  = (const float*)d_in[18]; const float* dbc1 = (const float*)d_in[19];
    const float* mW1   = (const float*)d_in[20]; const float* mb1  = (const float*)d_in[21];
    const float* mW2   = (const float*)d_in[22]; const float* mb2  = (const float*)d_in[23];
    const float* mem   = (const float*)d_in[24];
    const float* Wa    = (const float*)d_in[25];
    const float* fcw   = (const float*)d_in[26];
    const float* projW = (const float*)d_in[27];
    const float* projb = (const float*)d_in[28];
    float* outp = (float*)d_out;

    transpose_kernel<<<dim3(25,25), dim3(32,32)>>>(G);
    g2_kernel<<<dim3(7,7), 256>>>();

    auto fold = [](const float* W, int isGate, int widx, int P, int O) {
        int tot = 3*P*O;
        fold_kernel<<<(tot+255)/256, 256>>>(W, isGate, widx, P, O);
    };
    fold(eWg0,1,0,68,128);  fold(eWc0,0,0,68,64);
    fold(eWg1,1,1,128,128); fold(eWc1,0,1,128,64);
    fold(dWg0,1,2,68,128);  fold(dWc0,0,2,68,64);
    fold(dWg1,1,3,128,128); fold(dWc1,0,3,128,64);

    mlp_kernel<<<B_*T_,   256>>>(t_x, mW1, mb1, mW2, mb2, 0);
    mlp_kernel<<<B_*HOR_, 256>>>(t_y, mW1, mb1, mW2, mb2, 1);
    zero_state<<<(NB*H_+255)/256, 256>>>();

    auto cell0 = [&](int wsel, const float* bg, const float* bc) {
        prop2<<<dim3(34,13), 256>>>(0, 204, 0, 68, 136, 68);
        proj2<128,0><<<NB/128, 256>>>(0, 204, 204, wsel, bg, 0);
        build_fc0<<<(NB*76+255)/256, 256>>>();
        prop2<<<dim3(32,13), 256>>>(1, 204, 4, 72, 140, 64);
        proj2<64,1><<<NB/128, 256>>>(1, 204, 204, wsel, bc, 0);
    };
    auto cell1 = [&](int wsel, const float* bg, const float* bc) {
        prop2<<<dim3(64,13), 256>>>(0, 384, 0, 128, 256, 128);
        proj2<128,0><<<NB/128, 256>>>(0, 384, 384, wsel, bg, 1);
        build_rh1<<<(NB*64+255)/256, 256>>>();
        prop2<<<dim3(32,13), 256>>>(1, 384, 64, 192, 320, 64);
        proj2<64,1><<<NB/128, 256>>>(2, 384, 384, wsel, bc, 1);
    };

    // encoder
    for (int t = 0; t < T_; t++) {
        build_xh0<<<(NB*68+255)/256, 256>>>(x_seq, t, 0);
        cell0(0, ebg0, ebc0);
        build_xh1<<<(NB*128+255)/256, 256>>>();
        cell1(1, ebg1, ebc1);
    }
    // decoder
    for (int s = 0; s < HOR_; s++) {
        build_xh0<<<(NB*68+255)/256, 256>>>(x_seq, s, 1);
        cell0(2, dbg0, dbc0);
        build_xh1<<<(NB*128+255)/256, 256>>>();
        cell1(3, dbg1, dbc1);
        query_kernel<<<B_, 256>>>(Wa);
        attm_kernel<<<B_, 256>>>(mem, fcw);
        out_kernel<<<NB/256, 256>>>(projW, projb, outp, s);
    }
}

// round 7
// speedup vs baseline: 1.9106x; 1.9106x over previous
#include <cuda_runtime.h>
#include <cuda_bf16.h>
#include <stdint.h>
#include <math.h>

#define B_    64
#define T_    12
#define N_    800
#define CIN_  2
#define H_    64
#define HOR_  12
#define TC_H  2
#define KAPPA_ 0.05f
#define NB    (N_*B_)
#define CF0   208     /* layer0 feature stride (204 padded to 16-mult) */
#define CF1   384

// ---------------- device scratch ----------------
__device__ float g_A2[1600*800];                         // fp32 [GT; 2GT*GT - I]
__device__ __align__(16) __nv_bfloat16 g_A2h[1600*800];
__device__ __align__(16) __nv_bfloat16 g_A2l[1600*800];
__device__ float g_EMBX[B_*T_*N_*TC_H];
__device__ float g_EMBY[B_*HOR_*N_*TC_H];
__device__ float g_H0[NB*H_];
__device__ float g_H1[NB*H_];
__device__ float g_UR[NB*128];
__device__ float g_GO[NB*CIN_];
__device__ float g_Q [B_*8];
__device__ float g_ATTM[B_*N_*8];
__device__ __align__(16) __nv_bfloat16 g_Fh [NB*384];
__device__ __align__(16) __nv_bfloat16 g_Fl [NB*384];
__device__ __align__(16) __nv_bfloat16 g_FCh[NB*384];
__device__ __align__(16) __nv_bfloat16 g_FCl[NB*384];
__device__ __align__(16) __nv_bfloat16 g_WGh[4][384*128];
__device__ __align__(16) __nv_bfloat16 g_WGl[4][384*128];
__device__ __align__(16) __nv_bfloat16 g_WCh[4][384*64];
__device__ __align__(16) __nv_bfloat16 g_WCl[4][384*64];

// ---------------- helpers ----------------
__device__ __forceinline__ unsigned su(void* p) {
    return (unsigned)__cvta_generic_to_shared(p);
}
__device__ __forceinline__ void ldsm_x4(unsigned* r, unsigned addr) {
    asm volatile("ldmatrix.sync.aligned.m8n8.x4.shared.b16 {%0,%1,%2,%3},[%4];"
        : "=r"(r[0]),"=r"(r[1]),"=r"(r[2]),"=r"(r[3]) : "r"(addr));
}
__device__ __forceinline__ void ldsm_x2t(unsigned* r, unsigned addr) {
    asm volatile("ldmatrix.sync.aligned.m8n8.x2.trans.shared.b16 {%0,%1},[%2];"
        : "=r"(r[0]),"=r"(r[1]) : "r"(addr));
}
__device__ __forceinline__ void mma_bf16(float* c, const unsigned* a, const unsigned* b) {
    asm volatile("mma.sync.aligned.m16n8k16.row.col.f32.bf16.bf16.f32 "
        "{%0,%1,%2,%3},{%4,%5,%6,%7},{%8,%9},{%0,%1,%2,%3};"
        : "+f"(c[0]),"+f"(c[1]),"+f"(c[2]),"+f"(c[3])
        : "r"(a[0]),"r"(a[1]),"r"(a[2]),"r"(a[3]),"r"(b[0]),"r"(b[1]));
}
__device__ __forceinline__ void bsplit(float v, __nv_bfloat16* ph, __nv_bfloat16* pl) {
    __nv_bfloat16 h = __float2bfloat16(v);
    *ph = h;
    *pl = __float2bfloat16(v - __bfloat162float(h));
}

// ---------------- setup kernels ----------------
__global__ void transpose_kernel(const float* __restrict__ G) {
    __shared__ float t[32][33];
    int x = blockIdx.x*32 + threadIdx.x, y = blockIdx.y*32 + threadIdx.y;
    t[threadIdx.y][threadIdx.x] = G[y*N_ + x];
    __syncthreads();
    int x2 = blockIdx.y*32 + threadIdx.x, y2 = blockIdx.x*32 + threadIdx.y;
    g_A2[y2*N_ + x2] = t[threadIdx.x][threadIdx.y];
}

__global__ void __launch_bounds__(256) g2_kernel() {
    __shared__ float As[8][128], Bs[8][128];
    int tid = threadIdx.x;
    int i0 = blockIdx.y*128, j0 = blockIdx.x*128;
    int ty = tid>>4, tx = tid&15, rl = ty*4, cl = tx*4;
    int ar = tid>>1, ac = (tid&1)*4;
    int bk = tid>>5, bj = (tid&31)*4;
    float acc[8][8];
    #pragma unroll
    for (int i=0;i<8;i++) {
        #pragma unroll
        for (int j=0;j<8;j++) acc[i][j]=0.f;
    }
    for (int k0=0;k0<N_;k0+=8) {
        float4 av = make_float4(0,0,0,0);
        if (i0+ar < N_) av = *(const float4*)&g_A2[(long)(i0+ar)*N_ + k0+ac];
        As[ac+0][ar]=av.x; As[ac+1][ar]=av.y; As[ac+2][ar]=av.z; As[ac+3][ar]=av.w;
        float4 bv = make_float4(0,0,0,0);
        if (j0+bj < N_) bv = *(const float4*)&g_A2[(long)(k0+bk)*N_ + j0+bj];
        *(float4*)&Bs[bk][bj] = bv;
        __syncthreads();
        #pragma unroll
        for (int kk=0;kk<8;kk++) {
            float a[8], b[8];
            *(float4*)a     = *(const float4*)&As[kk][rl];
            *(float4*)(a+4) = *(const float4*)&As[kk][rl+64];
            *(float4*)b     = *(const float4*)&Bs[kk][cl];
            *(float4*)(b+4) = *(const float4*)&Bs[kk][cl+64];
            #pragma unroll
            for (int i=0;i<8;i++) {
                #pragma unroll
                for (int j=0;j<8;j++) acc[i][j] += a[i]*b[j];
            }
        }
        __syncthreads();
    }
    #pragma unroll
    for (int i=0;i<8;i++) {
        int r = i0 + (i<4 ? rl+i : 64+rl+i-4);
        if (r >= N_) continue;
        #pragma unroll
        for (int j=0;j<8;j++) {
            int c = j0 + (j<4 ? cl+j : 64+cl+j-4);
            if (c >= N_) continue;
            g_A2[(long)(N_+r)*N_ + c] = 2.f*acc[i][j] - (r==c ? 1.f : 0.f);
        }
    }
}

__global__ void split_a2() {
    int i = blockIdx.x*256 + threadIdx.x;
    if (i >= 1600*800) return;
    bsplit(g_A2[i], &g_A2h[i], &g_A2l[i]);
}

// fold kappa into k=0 block, split to bf16 hi/lo, zero-pad rows [3P, KT)
__global__ void fold_split(const float* __restrict__ W, int isGate, int widx,
                           int P, int O, int KT) {
    int idx = blockIdx.x*256 + threadIdx.x;
    if (idx >= KT*O) return;
    int row = idx / O, o = idx % O;
    float v = 0.f;
    if (row < 3*P) {
        int k = row / P, p = row % P;
        if (k == 0) v = W[idx] + KAPPA_*(W[(P+p)*O + o] + W[(2*P+p)*O + o]);
        else        v = (1.f - KAPPA_)*W[idx];
    }
    if (isGate) bsplit(v, &g_WGh[widx][idx], &g_WGl[widx][idx]);
    else        bsplit(v, &g_WCh[widx][idx], &g_WCl[widx][idx]);
}

__global__ void mlp_kernel(const float* __restrict__ Tin,
                           const float* __restrict__ W1, const float* __restrict__ b1,
                           const float* __restrict__ W2, const float* __restrict__ b2,
                           int dsel) {
    float* out = dsel ? g_EMBY : g_EMBX;
    int r = blockIdx.x, tid = threadIdx.x;
    __shared__ float tin[60];
    __shared__ float hid[10];
    if (tid < 60) tin[tid] = Tin[(long)r*60 + tid];
    __syncthreads();
    if (tid < 10) {
        float s = b1[tid];
        for (int i = 0; i < 60; i++) s += tin[i]*W1[i*10 + tid];
        hid[tid] = s;
    }
    __syncthreads();
    for (int o = tid; o < N_*TC_H; o += 256) {
        float s = b2[o];
        #pragma unroll
        for (int j = 0; j < 10; j++) s += hid[j]*W2[j*(N_*TC_H) + o];
        out[(long)r*(N_*TC_H) + o] = s;
    }
}

__global__ void zero_state() {
    int i = blockIdx.x*256 + threadIdx.x;
    if (i < NB*H_) { g_H0[i] = 0.f; g_H1[i] = 0.f; }
    if (i < NB*CIN_) g_GO[i] = 0.f;
    if (i < NB*4) {     // zero layer0 pad columns [204,208)
        int row = i >> 2, c = 204 + (i & 3);
        long a = (long)row*CF0 + c;
        __nv_bfloat16 z = __float2bfloat16(0.f);
        g_Fh[a] = z; g_Fl[a] = z; g_FCh[a] = z; g_FCl[a] = z;
    }
}

// ---------------- feature builders (write bf16 hi/lo) ----------------
__global__ void build_xh0(const float* __restrict__ xs, int t, int isDec) {
    int idx = blockIdx.x*256 + threadIdx.x;
    if (idx >= NB*68) return;
    int c = idx % 68, row = idx / 68;
    int b = row % B_, n = row / B_;
    float v;
    if (isDec) {
        if (c < 2)      v = g_GO[row*2 + c];
        else if (c < 4) v = g_EMBY[(long)(b*HOR_ + t)*(N_*TC_H) + n*TC_H + (c-2)];
        else            v = g_H0[(long)row*64 + (c-4)];
    } else {
        if (c < 2)      v = xs[((long)(b*T_ + t)*N_ + n)*CIN_ + c];
        else if (c < 4) v = g_EMBX[(long)(b*T_ + t)*(N_*TC_H) + n*TC_H + (c-2)];
        else            v = g_H0[(long)row*64 + (c-4)];
    }
    long a = (long)row*CF0 + c;
    bsplit(v, &g_Fh[a], &g_Fl[a]);
}

__global__ void build_xh1() {
    int idx = blockIdx.x*256 + threadIdx.x;
    if (idx >= NB*128) return;
    int c = idx % 128, row = idx / 128;
    float v = (c < 64) ? g_H0[(long)row*64 + c] : g_H1[(long)row*64 + (c-64)];
    long a = (long)row*CF1 + c;
    bsplit(v, &g_Fh[a], &g_Fl[a]);
}

__global__ void build_fc0() {
    int idx = blockIdx.x*256 + threadIdx.x;
    if (idx >= NB*76) return;
    int j = idx % 76, row = idx / 76;
    long base = (long)row*CF0;
    if (j < 4) {
        g_FCh[base+j] = g_Fh[base+j]; g_FCl[base+j] = g_Fl[base+j];
    } else if (j < 68) {
        int c = j - 4;
        float v = g_UR[(long)row*128 + 64 + c] * g_H0[(long)row*64 + c];
        bsplit(v, &g_FCh[base+j], &g_FCl[base+j]);
    } else if (j < 72) {
        int c = 68 + (j-68);
        g_FCh[base+c] = g_Fh[base+c]; g_FCl[base+c] = g_Fl[base+c];
    } else {
        int c = 136 + (j-72);
        g_FCh[base+c] = g_Fh[base+c]; g_FCl[base+c] = g_Fl[base+c];
    }
}

__global__ void build_rh1() {
    int idx = blockIdx.x*256 + threadIdx.x;
    if (idx >= NB*64) return;
    int c = idx & 63, row = idx >> 6;
    float v = g_UR[(long)row*128 + 64 + c] * g_H1[(long)row*64 + c];
    long a = (long)row*CF1 + 64 + c;
    bsplit(v, &g_FCh[a], &g_FCl[a]);
}

// ---------------- tensor-core graph propagation -------------------------------
// C[1600 x cols] = [GT;G2] @ F_slice0.   CTA tile 128(M) x 64(N), K-chunk 16.
// Split-3: acc += Ah*Bh + Ah*Bl + Al*Bh  (fp32 accumulate)
__global__ void __launch_bounds__(256) prop_tc(int bufSel, int CF, int src_off,
                                               int d1, int d2, int Psub) {
    const __nv_bfloat16* Fh = bufSel ? g_FCh : g_Fh;
    const __nv_bfloat16* Fl = bufSel ? g_FCl : g_Fl;
    __nv_bfloat16* Oh = bufSel ? g_FCh : g_Fh;
    __nv_bfloat16* Ol = bufSel ? g_FCl : g_Fl;
    __shared__ __align__(16) __nv_bfloat16 Ah[128][24], Al[128][24];
    __shared__ __align__(16) __nv_bfloat16 Bh[16][72],  Bl[16][72];
    int tid = threadIdx.x, lane = tid & 31, warp = tid >> 5;
    int m0 = blockIdx.y*128, n0 = blockIdx.x*64;
    int wm = warp >> 1, wn = warp & 1;        // 4x2 warp grid; warp tile 32x32
    float acc[2][4][4];
    #pragma unroll
    for (int i=0;i<2;i++)
        #pragma unroll
        for (int j=0;j<4;j++)
            #pragma unroll
            for (int e=0;e<4;e++) acc[i][j][e]=0.f;

    int ldRowA = tid >> 1, ldSegA = (tid & 1)*8;
    int grp = lane >> 3, rr = lane & 7;
    int arow = ((grp & 1) ? 8 : 0) + rr;
    int acol = (grp & 2) ? 8 : 0;
    int brow = lane & 15;

    for (int k0 = 0; k0 < 800; k0 += 16) {
        {   // A tile (128x16) hi+lo
            int gr = m0 + ldRowA;
            uint4 vh = make_uint4(0,0,0,0), vl = make_uint4(0,0,0,0);
            if (gr < 1600) {
                long a = (long)gr*800 + k0 + ldSegA;
                vh = *(const uint4*)&g_A2h[a];
                vl = *(const uint4*)&g_A2l[a];
            }
            *(uint4*)&Ah[ldRowA][ldSegA] = vh;
            *(uint4*)&Al[ldRowA][ldSegA] = vl;
        }
        // B tile (16x64) hi+lo — gathered over (batch,chan) columns
        for (int i = tid; i < 1024; i += 256) {
            int kr = i >> 6, c = i & 63;
            int j = n0 + c;
            int bo = j / Psub, co = j - bo*Psub;
            long a = ((long)(k0+kr)*B_ + bo)*CF + src_off + co;
            Bh[kr][c] = Fh[a];
            Bl[kr][c] = Fl[a];
        }
        __syncthreads();

        unsigned fah[2][4], fal[2][4], fbh[4][2], fbl[4][2];
        #pragma unroll
        for (int mi=0; mi<2; mi++) {
            ldsm_x4(fah[mi], su(&Ah[wm*32 + mi*16 + arow][acol]));
            ldsm_x4(fal[mi], su(&Al[wm*32 + mi*16 + arow][acol]));
        }
        #pragma unroll
        for (int ni=0; ni<4; ni++) {
            int c = wn*32 + ni*8;
            ldsm_x2t(fbh[ni], su(&Bh[brow][c]));
            ldsm_x2t(fbl[ni], su(&Bl[brow][c]));
        }
        #pragma unroll
        for (int mi=0; mi<2; mi++)
            #pragma unroll
            for (int ni=0; ni<4; ni++) {
                mma_bf16(acc[mi][ni], fah[mi], fbh[ni]);
                mma_bf16(acc[mi][ni], fah[mi], fbl[ni]);
                mma_bf16(acc[mi][ni], fal[mi], fbh[ni]);
            }
        __syncthreads();
    }

    // epilogue: split result to hi/lo and scatter into Y slices
    #pragma unroll
    for (int mi=0; mi<2; mi++)
        #pragma unroll
        for (int ni=0; ni<4; ni++) {
            int rb = m0 + wm*32 + mi*16 + (lane >> 2);
            int cb = n0 + wn*32 + ni*8 + 2*(lane & 3);
            #pragma unroll
            for (int e=0; e<4; e++) {
                int gr = rb + ((e >= 2) ? 8 : 0);
                int c  = cb + (e & 1);
                if (gr >= 1600) continue;
                int gm  = (gr < 800) ? gr : gr - 800;
                int off = (gr < 800) ? d1 : d2;
                int bo = c / Psub, co = c - bo*Psub;
                long a = ((long)gm*B_ + bo)*CF + off + co;
                bsplit(acc[mi][ni][e], &Oh[a], &Ol[a]);
            }
        }
}

// ---------------- tensor-core projection GEMM + fused GRU epilogues -----------
// MODE 0: UR = sigmoid(F @ Wg + bg)   NO=128
// MODE 1: H  = (1-u)h + u*tanh(A @ Wc + bc)  NO=64
// srcMode: 0 = F, 1 = FC, 2 = parity on (k>>6)&1
template<int NO, int MODE>
__global__ void __launch_bounds__(256) proj_tc(int srcMode, int CF, int KT, int wsel,
                                               const float* __restrict__ bias, int hsel) {
    const __nv_bfloat16* Wh = (MODE==0) ? g_WGh[wsel] : g_WCh[wsel];
    const __nv_bfloat16* Wl = (MODE==0) ? g_WGl[wsel] : g_WCl[wsel];
    constexpr int WN = NO/32;            // warps along N (4 or 2)
    constexpr int WM = 8/WN;             // warps along M (2 or 4)
    constexpr int MT = (128/WM)/16;      // m16 tiles per warp (4 or 2)
    __shared__ __align__(16) __nv_bfloat16 Ah[128][24], Al[128][24];
    __shared__ __align__(16) __nv_bfloat16 Bh[16][NO+8], Bl[16][NO+8];
    int tid = threadIdx.x, lane = tid & 31, warp = tid >> 5;
    long row0 = (long)blockIdx.x*128;
    int wm = warp / WN, wn = warp % WN;
    float acc[MT][4][4];
    #pragma unroll
    for (int i=0;i<MT;i++)
        #pragma unroll
        for (int j=0;j<4;j++)
            #pragma unroll
            for (int e=0;e<4;e++) acc[i][j][e]=0.f;

    int ldRowA = tid >> 1, ldSegA = (tid & 1)*8;
    int grp = lane >> 3, rr = lane & 7;
    int arow = ((grp & 1) ? 8 : 0) + rr;
    int acol = (grp & 2) ? 8 : 0;
    int brow = lane & 15;
    constexpr int WPER = 16*NO/8;        // uint4 loads for W tile

    for (int k0 = 0; k0 < KT; k0 += 16) {
        const __nv_bfloat16 *Sh, *Sl;
        if (srcMode == 0)      { Sh = g_Fh;  Sl = g_Fl; }
        else if (srcMode == 1) { Sh = g_FCh; Sl = g_FCl; }
        else if ((k0 >> 6) & 1){ Sh = g_FCh; Sl = g_FCl; }
        else                   { Sh = g_Fh;  Sl = g_Fl; }
        {   // A tile 128x16
            long a = (row0 + ldRowA)*CF + k0 + ldSegA;
            *(uint4*)&Ah[ldRowA][ldSegA] = *(const uint4*)&Sh[a];
            *(uint4*)&Al[ldRowA][ldSegA] = *(const uint4*)&Sl[a];
        }
        if (tid < WPER) {   // W tile 16xNO
            int row = tid / (NO/8), col = (tid % (NO/8))*8;
            long a = (long)(k0+row)*NO + col;
            *(uint4*)&Bh[row][col] = *(const uint4*)&Wh[a];
            *(uint4*)&Bl[row][col] = *(const uint4*)&Wl[a];
        }
        __syncthreads();

        unsigned fah[MT][4], fal[MT][4], fbh[4][2], fbl[4][2];
        #pragma unroll
        for (int mi=0; mi<MT; mi++) {
            ldsm_x4(fah[mi], su(&Ah[wm*(MT*16) + mi*16 + arow][acol]));
            ldsm_x4(fal[mi], su(&Al[wm*(MT*16) + mi*16 + arow][acol]));
        }
        #pragma unroll
        for (int ni=0; ni<4; ni++) {
            int c = wn*32 + ni*8;
            ldsm_x2t(fbh[ni], su(&Bh[brow][c]));
            ldsm_x2t(fbl[ni], su(&Bl[brow][c]));
        }
        #pragma unroll
        for (int mi=0; mi<MT; mi++)
            #pragma unroll
            for (int ni=0; ni<4; ni++) {
                mma_bf16(acc[mi][ni], fah[mi], fbh[ni]);
                mma_bf16(acc[mi][ni], fah[mi], fbl[ni]);
                mma_bf16(acc[mi][ni], fal[mi], fbh[ni]);
            }
        __syncthreads();
    }

    float* Hb = hsel ? g_H1 : g_H0;
    #pragma unroll
    for (int mi=0; mi<MT; mi++)
        #pragma unroll
        for (int ni=0; ni<4; ni++) {
            long rb = row0 + wm*(MT*16) + mi*16 + (lane >> 2);
            int  cb = wn*32 + ni*8 + 2*(lane & 3);
            #pragma unroll
            for (int e=0; e<4; e++) {
                long row = rb + ((e >= 2) ? 8 : 0);
                int  c   = cb + (e & 1);
                float v = acc[mi][ni][e] + bias[c];
                if (MODE == 0) {
                    g_UR[row*128 + c] = 1.f/(1.f + expf(-v));
                } else {
                    float cv = tanhf(v);
                    float u  = g_UR[row*128 + c];
                    float h  = Hb[row*64 + c];
                    Hb[row*64 + c] = (1.f - u)*h + u*cv;
                }
            }
        }
}

// ---------------- decoder memory attention + output projection ----------------
__global__ void query_kernel(const float* __restrict__ Wa) {
    int b = blockIdx.x, tid = threadIdx.x;
    float p[8];
    #pragma unroll
    for (int d = 0; d < 8; d++) p[d] = 0.f;
    for (int idx = tid; idx < N_*H_; idx += 256) {
        int n = idx >> 6, j = idx & 63;
        float v = g_H1[(long)(n*B_ + b)*64 + j];
        const float* w = Wa + (long)idx*8;
        #pragma unroll
        for (int d = 0; d < 8; d++) p[d] += v*w[d];
    }
    #pragma unroll
    for (int d = 0; d < 8; d++)
        for (int off = 16; off > 0; off >>= 1) p[d] += __shfl_down_sync(0xffffffffu, p[d], off);
    __shared__ float sm[8][8];
    int w = tid >> 5, l = tid & 31;
    if (l == 0) { for (int d = 0; d < 8; d++) sm[w][d] = p[d]; }
    __syncthreads();
    if (tid < 8) {
        float s = 0.f;
        for (int ww = 0; ww < 8; ww++) s += sm[ww][tid];
        g_Q[b*8 + tid] = s;
    }
}

__global__ void attm_kernel(const float* __restrict__ mem, const float* __restrict__ fcw) {
    int b = blockIdx.x, tid = threadIdx.x;
    __shared__ float am[8];
    if (tid == 0) {
        float q[8];
        for (int d = 0; d < 8; d++) q[d] = g_Q[b*8 + d];
        float s[4]; float mx = -1e30f;
        for (int m = 0; m < 4; m++) {
            float a = 0.f;
            for (int d = 0; d < 8; d++) a += q[d]*mem[m*8 + d];
            s[m] = a; mx = fmaxf(mx, a);
        }
        float den = 0.f;
        for (int m = 0; m < 4; m++) { s[m] = expf(s[m]-mx); den += s[m]; }
        for (int d = 0; d < 8; d++) {
            float a = 0.f;
            for (int m = 0; m < 4; m++) a += (s[m]/den)*mem[m*8 + d];
            am[d] = a;
        }
    }
    __syncthreads();
    for (int i = tid; i < N_*8; i += 256) {
        float s = 0.f;
        #pragma unroll
        for (int d = 0; d < 8; d++) s += am[d]*fcw[(long)d*(N_*8) + i];
        g_ATTM[(long)b*(N_*8) + i] = s;
    }
}

__global__ void out_kernel(const float* __restrict__ pW, const float* __restrict__ pb,
                           float* __restrict__ outp, int s) {
    int row = blockIdx.x*256 + threadIdx.x;
    if (row >= NB) return;
    int b = row % B_, n = row / B_;
    float a0 = pb[0], a1 = pb[1];
    const float* h = g_H1 + (long)row*64;
    #pragma unroll
    for (int j = 0; j < 64; j++) { float v = h[j]; a0 += v*pW[j*2]; a1 += v*pW[j*2+1]; }
    const float* at = g_ATTM + (long)b*(N_*8) + n*8;
    #pragma unroll
    for (int d = 0; d < 8; d++) { float v = at[d]; a0 += v*pW[(64+d)*2]; a1 += v*pW[(64+d)*2+1]; }
    a0 = fmaxf(a0, 0.f); a1 = fmaxf(a1, 0.f);
    g_GO[row*2] = a0; g_GO[row*2+1] = a1;
    long o = ((long)(b*HOR_ + s)*N_ + n)*CIN_;
    outp[o] = a0; outp[o+1] = a1;
}

// ---------------- orchestration ----------------
extern "C" void kernel_launch(void* const* d_in, const int* in_sizes, int n_in,
                              void* d_out, int out_size) {
    (void)in_sizes; (void)n_in; (void)out_size;
    const float* x_seq = (const float*)d_in[0];
    const float* t_x   = (const float*)d_in[1];
    const float* t_y   = (const float*)d_in[2];
    const float* G     = (const float*)d_in[3];
    const float* eWg0  = (const float*)d_in[4];  const float* ebg0 = (const float*)d_in[5];
    const float* eWc0  = (const float*)d_in[6];  const float* ebc0 = (const float*)d_in[7];
    const float* eWg1  = (const float*)d_in[8];  const float* ebg1 = (const float*)d_in[9];
    const float* eWc1  = (const float*)d_in[10]; const float* ebc1 = (const float*)d_in[11];
    const float* dWg0  = (const float*)d_in[12]; const float* dbg0 = (const float*)d_in[13];
    const float* dWc0  = (const float*)d_in[14]; const float* dbc0 = (const float*)d_in[15];
    const float* dWg1  = (const float*)d_in[16]; const float* dbg1 = (const float*)d_in[17];
    const float* dWc1  = (const float*)d_in[18]; const float* dbc1 = (const float*)d_in[19];
    const float* mW1   = (const float*)d_in[20]; const float* mb1  = (const float*)d_in[21];
    const float* mW2   = (const float*)d_in[22]; const float* mb2  = (const float*)d_in[23];
    const float* mem   = (const float*)d_in[24];
    const float* Wa    = (const float*)d_in[25];
    const float* fcw   = (const float*)d_in[26];
    const float* projW = (const float*)d_in[27];
    const float* projb = (const float*)d_in[28];
    float* outp = (float*)d_out;

    transpose_kernel<<<dim3(25,25), dim3(32,32)>>>(G);
    g2_kernel<<<dim3(7,7), 256>>>();
    split_a2<<<(1600*800+255)/256, 256>>>();

    auto fold = [](const float* W, int isGate, int widx, int P, int O) {
        int KT = ((3*P + 15)/16)*16;
        fold_split<<<(KT*O+255)/256, 256>>>(W, isGate, widx, P, O, KT);
    };
    fold(eWg0,1,0,68,128);  fold(eWc0,0,0,68,64);
    fold(eWg1,1,1,128,128); fold(eWc1,0,1,128,64);
    fold(dWg0,1,2,68,128);  fold(dWc0,0,2,68,64);
    fold(dWg1,1,3,128,128); fold(dWc1,0,3,128,64);

    mlp_kernel<<<B_*T_,   256>>>(t_x, mW1, mb1, mW2, mb2, 0);
    mlp_kernel<<<B_*HOR_, 256>>>(t_y, mW1, mb1, mW2, mb2, 1);
    zero_state<<<(NB*H_+255)/256, 256>>>();

    auto cell0 = [&](int wsel, const float* bg, const float* bc) {
        prop_tc<<<dim3(68,13), 256>>>(0, CF0, 0, 68, 136, 68);
        proj_tc<128,0><<<NB/128, 256>>>(0, CF0, 208, wsel, bg, 0);
        build_fc0<<<(NB*76+255)/256, 256>>>();
        prop_tc<<<dim3(64,13), 256>>>(1, CF0, 4, 72, 140, 64);
        proj_tc<64,1><<<NB/128, 256>>>(1, CF0, 208, wsel, bc, 0);
    };
    auto cell1 = [&](int wsel, const float* bg, const float* bc) {
        prop_tc<<<dim3(128,13), 256>>>(0, CF1, 0, 128, 256, 128);
        proj_tc<128,0><<<NB/128, 256>>>(0, CF1, 384, wsel, bg, 1);
        build_rh1<<<(NB*64+255)/256, 256>>>();
        prop_tc<<<dim3(64,13), 256>>>(1, CF1, 64, 192, 320, 64);
        proj_tc<64,1><<<NB/128, 256>>>(2, CF1, 384, wsel, bc, 1);
    };

    // encoder
    for (int t = 0; t < T_; t++) {
        build_xh0<<<(NB*68+255)/256, 256>>>(x_seq, t, 0);
        cell0(0, ebg0, ebc0);
        build_xh1<<<(NB*128+255)/256, 256>>>();
        cell1(1, ebg1, ebc1);
    }
    // decoder
    for (int s = 0; s < HOR_; s++) {
        build_xh0<<<(NB*68+255)/256, 256>>>(x_seq, s, 1);
        cell0(2, dbg0, dbc0);
        build_xh1<<<(NB*128+255)/256, 256>>>();
        cell1(3, dbg1, dbc1);
        query_kernel<<<B_, 256>>>(Wa);
        attm_kernel<<<B_, 256>>>(mem, fcw);
        out_kernel<<<NB/256, 256>>>(projW, projb, outp, s);
    }
}

// round 8
// speedup vs baseline: 3.4350x; 1.7978x over previous
#include <cuda_runtime.h>
#include <cuda_bf16.h>
#include <stdint.h>
#include <math.h>

#define B_    64
#define T_    12
#define N_    800
#define CIN_  2
#define H_    64
#define HOR_  12
#define TC_H  2
#define KAPPA_ 0.05f
#define NB    (N_*B_)
#define CF0   208
#define CF1   384
#define MPAD  1664    /* 1600 padded to 128-mult */

// ---------------- device scratch ----------------
__device__ float g_A2[1600*800];                         // fp32 [GT; 2GT*GT - I]
__device__ __align__(16) __nv_bfloat16 g_A2h[MPAD*800];
__device__ __align__(16) __nv_bfloat16 g_A2l[MPAD*800];
__device__ float g_EMBX[B_*T_*N_*TC_H];
__device__ float g_EMBY[B_*HOR_*N_*TC_H];
__device__ float g_H0[NB*H_];
__device__ float g_H1[NB*H_];
__device__ float g_UR[NB*128];
__device__ float g_GO[NB*CIN_];
__device__ float g_Q [B_*8];
__device__ float g_ATTM[B_*N_*8];
__device__ __align__(16) __nv_bfloat16 g_Fh [NB*384];
__device__ __align__(16) __nv_bfloat16 g_Fl [NB*384];
__device__ __align__(16) __nv_bfloat16 g_FCh[NB*384];
__device__ __align__(16) __nv_bfloat16 g_FCl[NB*384];
__device__ __align__(16) __nv_bfloat16 g_WGh[4][384*128];
__device__ __align__(16) __nv_bfloat16 g_WGl[4][384*128];
__device__ __align__(16) __nv_bfloat16 g_WCh[4][384*64];
__device__ __align__(16) __nv_bfloat16 g_WCl[4][384*64];

// ---------------- helpers ----------------
__device__ __forceinline__ unsigned su(void* p) {
    return (unsigned)__cvta_generic_to_shared(p);
}
__device__ __forceinline__ void cp16(void* dst, const void* src) {
    asm volatile("cp.async.ca.shared.global [%0],[%1],16;" :: "r"(su(dst)), "l"(src));
}
__device__ __forceinline__ void cp8(void* dst, const void* src) {
    asm volatile("cp.async.ca.shared.global [%0],[%1],8;" :: "r"(su(dst)), "l"(src));
}
__device__ __forceinline__ void cp_commit() {
    asm volatile("cp.async.commit_group;");
}
__device__ __forceinline__ void ldsm_x4(unsigned* r, unsigned addr) {
    asm volatile("ldmatrix.sync.aligned.m8n8.x4.shared.b16 {%0,%1,%2,%3},[%4];"
        : "=r"(r[0]),"=r"(r[1]),"=r"(r[2]),"=r"(r[3]) : "r"(addr));
}
__device__ __forceinline__ void ldsm_x2t(unsigned* r, unsigned addr) {
    asm volatile("ldmatrix.sync.aligned.m8n8.x2.trans.shared.b16 {%0,%1},[%2];"
        : "=r"(r[0]),"=r"(r[1]) : "r"(addr));
}
__device__ __forceinline__ void mma_bf16(float* c, const unsigned* a, const unsigned* b) {
    asm volatile("mma.sync.aligned.m16n8k16.row.col.f32.bf16.bf16.f32 "
        "{%0,%1,%2,%3},{%4,%5,%6,%7},{%8,%9},{%0,%1,%2,%3};"
        : "+f"(c[0]),"+f"(c[1]),"+f"(c[2]),"+f"(c[3])
        : "r"(a[0]),"r"(a[1]),"r"(a[2]),"r"(a[3]),"r"(b[0]),"r"(b[1]));
}
__device__ __forceinline__ void bsplit(float v, __nv_bfloat16* ph, __nv_bfloat16* pl) {
    __nv_bfloat16 h = __float2bfloat16(v);
    *ph = h;
    *pl = __float2bfloat16(v - __bfloat162float(h));
}

// ---------------- setup kernels ----------------
__global__ void transpose_kernel(const float* __restrict__ G) {
    __shared__ float t[32][33];
    int x = blockIdx.x*32 + threadIdx.x, y = blockIdx.y*32 + threadIdx.y;
    t[threadIdx.y][threadIdx.x] = G[y*N_ + x];
    __syncthreads();
    int x2 = blockIdx.y*32 + threadIdx.x, y2 = blockIdx.x*32 + threadIdx.y;
    g_A2[y2*N_ + x2] = t[threadIdx.x][threadIdx.y];
}

__global__ void __launch_bounds__(256) g2_kernel() {
    __shared__ float As[8][128], Bs[8][128];
    int tid = threadIdx.x;
    int i0 = blockIdx.y*128, j0 = blockIdx.x*128;
    int ty = tid>>4, tx = tid&15, rl = ty*4, cl = tx*4;
    int ar = tid>>1, ac = (tid&1)*4;
    int bk = tid>>5, bj = (tid&31)*4;
    float acc[8][8];
    #pragma unroll
    for (int i=0;i<8;i++) {
        #pragma unroll
        for (int j=0;j<8;j++) acc[i][j]=0.f;
    }
    for (int k0=0;k0<N_;k0+=8) {
        float4 av = make_float4(0,0,0,0);
        if (i0+ar < N_) av = *(const float4*)&g_A2[(long)(i0+ar)*N_ + k0+ac];
        As[ac+0][ar]=av.x; As[ac+1][ar]=av.y; As[ac+2][ar]=av.z; As[ac+3][ar]=av.w;
        float4 bv = make_float4(0,0,0,0);
        if (j0+bj < N_) bv = *(const float4*)&g_A2[(long)(k0+bk)*N_ + j0+bj];
        *(float4*)&Bs[bk][bj] = bv;
        __syncthreads();
        #pragma unroll
        for (int kk=0;kk<8;kk++) {
            float a[8], b[8];
            *(float4*)a     = *(const float4*)&As[kk][rl];
            *(float4*)(a+4) = *(const float4*)&As[kk][rl+64];
            *(float4*)b     = *(const float4*)&Bs[kk][cl];
            *(float4*)(b+4) = *(const float4*)&Bs[kk][cl+64];
            #pragma unroll
            for (int i=0;i<8;i++) {
                #pragma unroll
                for (int j=0;j<8;j++) acc[i][j] += a[i]*b[j];
            }
        }
        __syncthreads();
    }
    #pragma unroll
    for (int i=0;i<8;i++) {
        int r = i0 + (i<4 ? rl+i : 64+rl+i-4);
        if (r >= N_) continue;
        #pragma unroll
        for (int j=0;j<8;j++) {
            int c = j0 + (j<4 ? cl+j : 64+cl+j-4);
            if (c >= N_) continue;
            g_A2[(long)(N_+r)*N_ + c] = 2.f*acc[i][j] - (r==c ? 1.f : 0.f);
        }
    }
}

__global__ void split_a2() {
    int i = blockIdx.x*256 + threadIdx.x;
    if (i >= MPAD*800) return;
    float v = (i < 1600*800) ? g_A2[i] : 0.f;
    bsplit(v, &g_A2h[i], &g_A2l[i]);
}

__global__ void fold_split(const float* __restrict__ W, int isGate, int widx,
                           int P, int O, int KT) {
    int idx = blockIdx.x*256 + threadIdx.x;
    if (idx >= KT*O) return;
    int row = idx / O, o = idx % O;
    float v = 0.f;
    if (row < 3*P) {
        int k = row / P, p = row % P;
        if (k == 0) v = W[idx] + KAPPA_*(W[(P+p)*O + o] + W[(2*P+p)*O + o]);
        else        v = (1.f - KAPPA_)*W[idx];
    }
    if (isGate) bsplit(v, &g_WGh[widx][idx], &g_WGl[widx][idx]);
    else        bsplit(v, &g_WCh[widx][idx], &g_WCl[widx][idx]);
}

__global__ void mlp_kernel(const float* __restrict__ Tin,
                           const float* __restrict__ W1, const float* __restrict__ b1,
                           const float* __restrict__ W2, const float* __restrict__ b2,
                           int dsel) {
    float* out = dsel ? g_EMBY : g_EMBX;
    int r = blockIdx.x, tid = threadIdx.x;
    __shared__ float tin[60];
    __shared__ float hid[10];
    if (tid < 60) tin[tid] = Tin[(long)r*60 + tid];
    __syncthreads();
    if (tid < 10) {
        float s = b1[tid];
        for (int i = 0; i < 60; i++) s += tin[i]*W1[i*10 + tid];
        hid[tid] = s;
    }
    __syncthreads();
    for (int o = tid; o < N_*TC_H; o += 256) {
        float s = b2[o];
        #pragma unroll
        for (int j = 0; j < 10; j++) s += hid[j]*W2[j*(N_*TC_H) + o];
        out[(long)r*(N_*TC_H) + o] = s;
    }
}

__global__ void zero_state() {
    int i = blockIdx.x*256 + threadIdx.x;
    if (i < NB*H_) { g_H0[i] = 0.f; g_H1[i] = 0.f; }
    if (i < NB*CIN_) g_GO[i] = 0.f;
    if (i < NB*4) {
        int row = i >> 2, c = 204 + (i & 3);
        long a = (long)row*CF0 + c;
        __nv_bfloat16 z = __float2bfloat16(0.f);
        g_Fh[a] = z; g_Fl[a] = z; g_FCh[a] = z; g_FCl[a] = z;
    }
}

// ---------------- feature builders ----------------
__global__ void build_xh0(const float* __restrict__ xs, int t, int isDec) {
    int idx = blockIdx.x*256 + threadIdx.x;
    if (idx >= NB*68) return;
    int c = idx % 68, row = idx / 68;
    int b = row % B_, n = row / B_;
    float v;
    if (isDec) {
        if (c < 2)      v = g_GO[row*2 + c];
        else if (c < 4) v = g_EMBY[(long)(b*HOR_ + t)*(N_*TC_H) + n*TC_H + (c-2)];
        else            v = g_H0[(long)row*64 + (c-4)];
    } else {
        if (c < 2)      v = xs[((long)(b*T_ + t)*N_ + n)*CIN_ + c];
        else if (c < 4) v = g_EMBX[(long)(b*T_ + t)*(N_*TC_H) + n*TC_H + (c-2)];
        else            v = g_H0[(long)row*64 + (c-4)];
    }
    long a = (long)row*CF0 + c;
    bsplit(v, &g_Fh[a], &g_Fl[a]);
}

__global__ void build_xh1() {
    int idx = blockIdx.x*256 + threadIdx.x;
    if (idx >= NB*128) return;
    int c = idx % 128, row = idx / 128;
    float v = (c < 64) ? g_H0[(long)row*64 + c] : g_H1[(long)row*64 + (c-64)];
    long a = (long)row*CF1 + c;
    bsplit(v, &g_Fh[a], &g_Fl[a]);
}

__global__ void build_fc0() {
    int idx = blockIdx.x*256 + threadIdx.x;
    if (idx >= NB*76) return;
    int j = idx % 76, row = idx / 76;
    long base = (long)row*CF0;
    if (j < 4) {
        g_FCh[base+j] = g_Fh[base+j]; g_FCl[base+j] = g_Fl[base+j];
    } else if (j < 68) {
        int c = j - 4;
        float v = g_UR[(long)row*128 + 64 + c] * g_H0[(long)row*64 + c];
        bsplit(v, &g_FCh[base+j], &g_FCl[base+j]);
    } else if (j < 72) {
        int c = 68 + (j-68);
        g_FCh[base+c] = g_Fh[base+c]; g_FCl[base+c] = g_Fl[base+c];
    } else {
        int c = 136 + (j-72);
        g_FCh[base+c] = g_Fh[base+c]; g_FCl[base+c] = g_Fl[base+c];
    }
}

__global__ void build_rh1() {
    int idx = blockIdx.x*256 + threadIdx.x;
    if (idx >= NB*64) return;
    int c = idx & 63, row = idx >> 6;
    float v = g_UR[(long)row*128 + 64 + c] * g_H1[(long)row*64 + c];
    long a = (long)row*CF1 + 64 + c;
    bsplit(v, &g_FCh[a], &g_FCl[a]);
}

// ---------------- tensor-core graph propagation (cp.async, 128x128 tile) ------
__global__ void __launch_bounds__(256) prop_tc(int bufSel, int CF, int src_off,
                                               int d1, int d2, int Psub) {
    const __nv_bfloat16* Fh = bufSel ? g_FCh : g_Fh;
    const __nv_bfloat16* Fl = bufSel ? g_FCl : g_Fl;
    __nv_bfloat16* Oh = bufSel ? g_FCh : g_Fh;
    __nv_bfloat16* Ol = bufSel ? g_FCl : g_Fl;
    __shared__ __align__(16) __nv_bfloat16 Ah[2][128][24], Al[2][128][24];
    __shared__ __align__(16) __nv_bfloat16 Bh[2][16][136], Bl[2][16][136];
    int tid = threadIdx.x, lane = tid & 31, warp = tid >> 5;
    int m0 = blockIdx.y*128, n0 = blockIdx.x*128;
    int wm = warp >> 2, wn = warp & 3;          // 2x4 warps; warp tile 64x32
    long rowStride = (long)B_*CF;

    float acc[4][4][4];
    #pragma unroll
    for (int i=0;i<4;i++)
        #pragma unroll
        for (int j=0;j<4;j++)
            #pragma unroll
            for (int e=0;e<4;e++) acc[i][j][e]=0.f;

    // loader geometry (chunk-invariant)
    int aRow = tid >> 1, aSeg = (tid & 1)*8;
    long aBase = (long)(m0 + aRow)*800 + aSeg;     // m0+aRow < MPAD
    int kr0 = tid >> 5,        cc0 = (tid & 31)*4;
    int kr1 = (tid+256) >> 5,  cc1 = (tid & 31)*4;
    int j0g = n0 + cc0, j1g = n0 + cc1;
    int bo0 = j0g/Psub, co0 = j0g - bo0*Psub;
    int bo1 = j1g/Psub, co1 = j1g - bo1*Psub;
    long bOff0 = (long)bo0*CF + src_off + co0;
    long bOff1 = (long)bo1*CF + src_off + co1;

    auto issue = [&](int k0, int s) {
        cp16(&Ah[s][aRow][aSeg], g_A2h + aBase + k0);
        cp16(&Al[s][aRow][aSeg], g_A2l + aBase + k0);
        long a0 = (long)(k0+kr0)*rowStride + bOff0;
        long a1 = (long)(k0+kr1)*rowStride + bOff1;
        cp8(&Bh[s][kr0][cc0], Fh + a0);
        cp8(&Bl[s][kr0][cc0], Fl + a0);
        cp8(&Bh[s][kr1][cc1], Fh + a1);
        cp8(&Bl[s][kr1][cc1], Fl + a1);
        cp_commit();
    };

    int grp = lane >> 3, rr = lane & 7;
    int arow = ((grp & 1) ? 8 : 0) + rr;
    int acol = (grp & 2) ? 8 : 0;
    int brow = lane & 15;

    issue(0, 0);
    for (int c = 0; c < 50; c++) {
        if (c < 49) { issue((c+1)*16, (c+1)&1); asm volatile("cp.async.wait_group 1;"); }
        else        { asm volatile("cp.async.wait_group 0;"); }
        __syncthreads();
        int s = c & 1;
        unsigned fah[4][4], fal[4][4], fbh[4][2], fbl[4][2];
        #pragma unroll
        for (int mi=0; mi<4; mi++) {
            ldsm_x4(fah[mi], su(&Ah[s][wm*64 + mi*16 + arow][acol]));
            ldsm_x4(fal[mi], su(&Al[s][wm*64 + mi*16 + arow][acol]));
        }
        #pragma unroll
        for (int ni=0; ni<4; ni++) {
            ldsm_x2t(fbh[ni], su(&Bh[s][brow][wn*32 + ni*8]));
            ldsm_x2t(fbl[ni], su(&Bl[s][brow][wn*32 + ni*8]));
        }
        #pragma unroll
        for (int mi=0; mi<4; mi++)
            #pragma unroll
            for (int ni=0; ni<4; ni++) {
                mma_bf16(acc[mi][ni], fah[mi], fbh[ni]);
                mma_bf16(acc[mi][ni], fah[mi], fbl[ni]);
                mma_bf16(acc[mi][ni], fal[mi], fbh[ni]);
            }
        __syncthreads();
    }

    // epilogue: bf162 paired stores
    #pragma unroll
    for (int mi=0; mi<4; mi++)
        #pragma unroll
        for (int ni=0; ni<4; ni++) {
            int rb = m0 + wm*64 + mi*16 + (lane >> 2);
            int cb = n0 + wn*32 + ni*8 + 2*(lane & 3);
            int bo = cb / Psub, co = cb - bo*Psub;
            #pragma unroll
            for (int hh=0; hh<2; hh++) {
                int gr = rb + hh*8;
                if (gr >= 1600) continue;
                int gm  = (gr < 800) ? gr : gr - 800;
                int off = (gr < 800) ? d1 : d2;
                long a = (long)gm*rowStride + (long)bo*CF + off + co;
                float v0 = acc[mi][ni][2*hh], v1 = acc[mi][ni][2*hh+1];
                __nv_bfloat16 h0 = __float2bfloat16(v0);
                __nv_bfloat16 h1 = __float2bfloat16(v1);
                __nv_bfloat16 l0 = __float2bfloat16(v0 - __bfloat162float(h0));
                __nv_bfloat16 l1 = __float2bfloat16(v1 - __bfloat162float(h1));
                *(__nv_bfloat162*)&Oh[a] = __halves2bfloat162(h0, h1);
                *(__nv_bfloat162*)&Ol[a] = __halves2bfloat162(l0, l1);
            }
        }
}

// ---------------- tensor-core projection (cp.async) + fused GRU epilogues -----
template<int NO, int MODE>
__global__ void __launch_bounds__(256) proj_tc(int srcMode, int CF, int KT, int wsel,
                                               const float* __restrict__ bias, int hsel) {
    const __nv_bfloat16* Wh = (MODE==0) ? g_WGh[wsel] : g_WCh[wsel];
    const __nv_bfloat16* Wl = (MODE==0) ? g_WGl[wsel] : g_WCl[wsel];
    constexpr int WN = NO/32;
    constexpr int WM = 8/WN;
    constexpr int MT = (128/WM)/16;
    __shared__ __align__(16) __nv_bfloat16 Ah[2][128][24], Al[2][128][24];
    __shared__ __align__(16) __nv_bfloat16 Bh[2][16][NO+8], Bl[2][16][NO+8];
    int tid = threadIdx.x, lane = tid & 31, warp = tid >> 5;
    long row0 = (long)blockIdx.x*128;
    int wm = warp / WN, wn = warp % WN;
    float acc[MT][4][4];
    #pragma unroll
    for (int i=0;i<MT;i++)
        #pragma unroll
        for (int j=0;j<4;j++)
            #pragma unroll
            for (int e=0;e<4;e++) acc[i][j][e]=0.f;

    int aRow = tid >> 1, aSeg = (tid & 1)*8;
    long aBase = (row0 + aRow)*CF + aSeg;

    auto issue = [&](int k0, int s) {
        const __nv_bfloat16 *Sh, *Sl;
        if (srcMode == 0)       { Sh = g_Fh;  Sl = g_Fl; }
        else if (srcMode == 1)  { Sh = g_FCh; Sl = g_FCl; }
        else if ((k0 >> 6) & 1) { Sh = g_FCh; Sl = g_FCl; }
        else                    { Sh = g_Fh;  Sl = g_Fl; }
        cp16(&Ah[s][aRow][aSeg], Sh + aBase + k0);
        cp16(&Al[s][aRow][aSeg], Sl + aBase + k0);
        if (NO == 128) {
            int wr = tid >> 4, wc = (tid & 15)*8;
            long a = (long)(k0+wr)*NO + wc;
            cp16(&Bh[s][wr][wc], Wh + a);
            cp16(&Bl[s][wr][wc], Wl + a);
        } else if (tid < 128) {
            int wr = tid >> 3, wc = (tid & 7)*8;
            long a = (long)(k0+wr)*NO + wc;
            cp16(&Bh[s][wr][wc], Wh + a);
            cp16(&Bl[s][wr][wc], Wl + a);
        }
        cp_commit();
    };

    int grp = lane >> 3, rr = lane & 7;
    int arow = ((grp & 1) ? 8 : 0) + rr;
    int acol = (grp & 2) ? 8 : 0;
    int brow = lane & 15;

    int NC = KT / 16;
    issue(0, 0);
    for (int c = 0; c < NC; c++) {
        if (c < NC-1) { issue((c+1)*16, (c+1)&1); asm volatile("cp.async.wait_group 1;"); }
        else          { asm volatile("cp.async.wait_group 0;"); }
        __syncthreads();
        int s = c & 1;
        unsigned fah[MT][4], fal[MT][4], fbh[4][2], fbl[4][2];
        #pragma unroll
        for (int mi=0; mi<MT; mi++) {
            ldsm_x4(fah[mi], su(&Ah[s][wm*(MT*16) + mi*16 + arow][acol]));
            ldsm_x4(fal[mi], su(&Al[s][wm*(MT*16) + mi*16 + arow][acol]));
        }
        #pragma unroll
        for (int ni=0; ni<4; ni++) {
            int cc = wn*32 + ni*8;
            ldsm_x2t(fbh[ni], su(&Bh[s][brow][cc]));
            ldsm_x2t(fbl[ni], su(&Bl[s][brow][cc]));
        }
        #pragma unroll
        for (int mi=0; mi<MT; mi++)
            #pragma unroll
            for (int ni=0; ni<4; ni++) {
                mma_bf16(acc[mi][ni], fah[mi], fbh[ni]);
                mma_bf16(acc[mi][ni], fah[mi], fbl[ni]);
                mma_bf16(acc[mi][ni], fal[mi], fbh[ni]);
            }
        __syncthreads();
    }

    float* Hb = hsel ? g_H1 : g_H0;
    #pragma unroll
    for (int mi=0; mi<MT; mi++)
        #pragma unroll
        for (int ni=0; ni<4; ni++) {
            long rb = row0 + wm*(MT*16) + mi*16 + (lane >> 2);
            int  cb = wn*32 + ni*8 + 2*(lane & 3);
            #pragma unroll
            for (int e=0; e<4; e++) {
                long row = rb + ((e >= 2) ? 8 : 0);
                int  c   = cb + (e & 1);
                float v = acc[mi][ni][e] + bias[c];
                if (MODE == 0) {
                    g_UR[row*128 + c] = 1.f/(1.f + expf(-v));
                } else {
                    float cv = tanhf(v);
                    float u  = g_UR[row*128 + c];
                    float h  = Hb[row*64 + c];
                    Hb[row*64 + c] = (1.f - u)*h + u*cv;
                }
            }
        }
}

// ---------------- decoder memory attention + output projection ----------------
__global__ void query_kernel(const float* __restrict__ Wa) {
    int b = blockIdx.x, tid = threadIdx.x;
    float p[8];
    #pragma unroll
    for (int d = 0; d < 8; d++) p[d] = 0.f;
    for (int idx = tid; idx < N_*H_; idx += 256) {
        int n = idx >> 6, j = idx & 63;
        float v = g_H1[(long)(n*B_ + b)*64 + j];
        const float* w = Wa + (long)idx*8;
        #pragma unroll
        for (int d = 0; d < 8; d++) p[d] += v*w[d];
    }
    #pragma unroll
    for (int d = 0; d < 8; d++)
        for (int off = 16; off > 0; off >>= 1) p[d] += __shfl_down_sync(0xffffffffu, p[d], off);
    __shared__ float sm[8][8];
    int w = tid >> 5, l = tid & 31;
    if (l == 0) { for (int d = 0; d < 8; d++) sm[w][d] = p[d]; }
    __syncthreads();
    if (tid < 8) {
        float s = 0.f;
        for (int ww = 0; ww < 8; ww++) s += sm[ww][tid];
        g_Q[b*8 + tid] = s;
    }
}

__global__ void attm_kernel(const float* __restrict__ mem, const float* __restrict__ fcw) {
    int b = blockIdx.x, tid = threadIdx.x;
    __shared__ float am[8];
    if (tid == 0) {
        float q[8];
        for (int d = 0; d < 8; d++) q[d] = g_Q[b*8 + d];
        float s[4]; float mx = -1e30f;
        for (int m = 0; m < 4; m++) {
            float a = 0.f;
            for (int d = 0; d < 8; d++) a += q[d]*mem[m*8 + d];
            s[m] = a; mx = fmaxf(mx, a);
        }
        float den = 0.f;
        for (int m = 0; m < 4; m++) { s[m] = expf(s[m]-mx); den += s[m]; }
        for (int d = 0; d < 8; d++) {
            float a = 0.f;
            for (int m = 0; m < 4; m++) a += (s[m]/den)*mem[m*8 + d];
            am[d] = a;
        }
    }
    __syncthreads();
    for (int i = tid; i < N_*8; i += 256) {
        float s = 0.f;
        #pragma unroll
        for (int d = 0; d < 8; d++) s += am[d]*fcw[(long)d*(N_*8) + i];
        g_ATTM[(long)b*(N_*8) + i] = s;
    }
}

__global__ void out_kernel(const float* __restrict__ pW, const float* __restrict__ pb,
                           float* __restrict__ outp, int s) {
    int row = blockIdx.x*256 + threadIdx.x;
    if (row >= NB) return;
    int b = row % B_, n = row / B_;
    float a0 = pb[0], a1 = pb[1];
    const float* h = g_H1 + (long)row*64;
    #pragma unroll
    for (int j = 0; j < 64; j++) { float v = h[j]; a0 += v*pW[j*2]; a1 += v*pW[j*2+1]; }
    const float* at = g_ATTM + (long)b*(N_*8) + n*8;
    #pragma unroll
    for (int d = 0; d < 8; d++) { float v = at[d]; a0 += v*pW[(64+d)*2]; a1 += v*pW[(64+d)*2+1]; }
    a0 = fmaxf(a0, 0.f); a1 = fmaxf(a1, 0.f);
    g_GO[row*2] = a0; g_GO[row*2+1] = a1;
    long o = ((long)(b*HOR_ + s)*N_ + n)*CIN_;
    outp[o] = a0; outp[o+1] = a1;
}

// ---------------- orchestration ----------------
extern "C" void kernel_launch(void* const* d_in, const int* in_sizes, int n_in,
                              void* d_out, int out_size) {
    (void)in_sizes; (void)n_in; (void)out_size;
    const float* x_seq = (const float*)d_in[0];
    const float* t_x   = (const float*)d_in[1];
    const float* t_y   = (const float*)d_in[2];
    const float* G     = (const float*)d_in[3];
    const float* eWg0  = (const float*)d_in[4];  const float* ebg0 = (const float*)d_in[5];
    const float* eWc0  = (const float*)d_in[6];  const float* ebc0 = (const float*)d_in[7];
    const float* eWg1  = (const float*)d_in[8];  const float* ebg1 = (const float*)d_in[9];
    const float* eWc1  = (const float*)d_in[10]; const float* ebc1 = (const float*)d_in[11];
    const float* dWg0  = (const float*)d_in[12]; const float* dbg0 = (const float*)d_in[13];
    const float* dWc0  = (const float*)d_in[14]; const float* dbc0 = (const float*)d_in[15];
    const float* dWg1  = (const float*)d_in[16]; const float* dbg1 = (const float*)d_in[17];
    const float* dWc1  = (const float*)d_in[18]; const float* dbc1 = (const float*)d_in[19];
    const float* mW1   = (const float*)d_in[20]; const float* mb1  = (const float*)d_in[21];
    const float* mW2   = (const float*)d_in[22]; const float* mb2  = (const float*)d_in[23];
    const float* mem   = (const float*)d_in[24];
    const float* Wa    = (const float*)d_in[25];
    const float* fcw   = (const float*)d_in[26];
    const float* projW = (const float*)d_in[27];
    const float* projb = (const float*)d_in[28];
    float* outp = (float*)d_out;

    transpose_kernel<<<dim3(25,25), dim3(32,32)>>>(G);
    g2_kernel<<<dim3(7,7), 256>>>();
    split_a2<<<(MPAD*800+255)/256, 256>>>();

    auto fold = [](const float* W, int isGate, int widx, int P, int O) {
        int KT = ((3*P + 15)/16)*16;
        fold_split<<<(KT*O+255)/256, 256>>>(W, isGate, widx, P, O, KT);
    };
    fold(eWg0,1,0,68,128);  fold(eWc0,0,0,68,64);
    fold(eWg1,1,1,128,128); fold(eWc1,0,1,128,64);
    fold(dWg0,1,2,68,128);  fold(dWc0,0,2,68,64);
    fold(dWg1,1,3,128,128); fold(dWc1,0,3,128,64);

    mlp_kernel<<<B_*T_,   256>>>(t_x, mW1, mb1, mW2, mb2, 0);
    mlp_kernel<<<B_*HOR_, 256>>>(t_y, mW1, mb1, mW2, mb2, 1);
    zero_state<<<(NB*H_+255)/256, 256>>>();

    auto cell0 = [&](int wsel, const float* bg, const float* bc) {
        prop_tc<<<dim3(34,13), 256>>>(0, CF0, 0, 68, 136, 68);   // 4352 cols
        proj_tc<128,0><<<NB/128, 256>>>(0, CF0, 208, wsel, bg, 0);
        build_fc0<<<(NB*76+255)/256, 256>>>();
        prop_tc<<<dim3(32,13), 256>>>(1, CF0, 4, 72, 140, 64);   // 4096 cols
        proj_tc<64,1><<<NB/128, 256>>>(1, CF0, 208, wsel, bc, 0);
    };
    auto cell1 = [&](int wsel, const float* bg, const float* bc) {
        prop_tc<<<dim3(64,13), 256>>>(0, CF1, 0, 128, 256, 128); // 8192 cols
        proj_tc<128,0><<<NB/128, 256>>>(0, CF1, 384, wsel, bg, 1);
        build_rh1<<<(NB*64+255)/256, 256>>>();
        prop_tc<<<dim3(32,13), 256>>>(1, CF1, 64, 192, 320, 64); // 4096 cols
        proj_tc<64,1><<<NB/128, 256>>>(2, CF1, 384, wsel, bc, 1);
    };

    // encoder
    for (int t = 0; t < T_; t++) {
        build_xh0<<<(NB*68+255)/256, 256>>>(x_seq, t, 0);
        cell0(0, ebg0, ebc0);
        build_xh1<<<(NB*128+255)/256, 256>>>();
        cell1(1, ebg1, ebc1);
    }
    // decoder
    for (int s = 0; s < HOR_; s++) {
        build_xh0<<<(NB*68+255)/256, 256>>>(x_seq, s, 1);
        cell0(2, dbg0, dbc0);
        build_xh1<<<(NB*128+255)/256, 256>>>();
        cell1(3, dbg1, dbc1);
        query_kernel<<<B_, 256>>>(Wa);
        attm_kernel<<<B_, 256>>>(mem, fcw);
        out_kernel<<<NB/256, 256>>>(projW, projb, outp, s);
    }
}